// round 13
// baseline (speedup 1.0000x reference)
#include <cuda_runtime.h>
#include <cstdint>

// Problem constants
#define NBATCH 64
#define NBINS  256
#define ELEMS_PER_BATCH (256*32*32)          // 262144 floats per batch per tensor
#define F4_PER_BATCH    (ELEMS_PER_BATCH/4)  // 65536 float4
#define CHUNKS 2                             // blocks per (batch, tensor)
#define F4_PER_CHUNK (F4_PER_BATCH/CHUNKS)   // 32768 float4 per block
#define HIST_THREADS 512
#define NWARPS 16
#define SMEM_WARPS 12                        // warps on the smem ATOMS unit
#define F4_PER_WARP (F4_PER_CHUNK/NWARPS)    // 2048 float4 per warp
#define WARP_ITERS (F4_PER_WARP/32)          // 64 iterations of 32 f4
#define BLOCKS_PER_BATCH (2*CHUNKS)          // 4 (both tensors)

// Scratch (no device allocation allowed).
__device__ unsigned int g_part[2][NBATCH][CHUNKS][NBINS];
__device__ unsigned int g_dir[2][NBATCH][NBINS];   // L2-atomic (REDG) histogram
__device__ float        g_kl[NBATCH];
__device__ unsigned int g_bctr[NBATCH];      // per-batch tickets (reset by winner)
__device__ unsigned int g_ctr;               // global ticket (reset by final block)

// Exact float->small-int for integer-valued f in [0,255]: low byte of
// bits(f + 2^23). Avoids the F2I conversion pipe.
__device__ __forceinline__ unsigned int bin_of(float f) {
    return __float_as_uint(f + 8388608.0f) & 0xFFu;
}

// ---------------------------------------------------------------------------
// Single fused kernel. grid = (CHUNKS, NBATCH, 2) = 256 blocks, block = 512.
// Warps 0..11 : smem-atomic histogram, bank-exclusive sh[bin][lane], 8-deep
//               register MLP batch (proven R7 path).
// Warps 12..15: fire-and-forget global RED.ADD into g_dir — routed to the
//               192 LTS atomic units, entirely off the SM's ATOMS unit and
//               off the vote pipe. No scoreboard wait (no return value).
// Both units count concurrently; per-warp element quotas are uniform because
// the measured rates (4.2 vs ~1.3 lanes/cyc/SM) roughly match the 12:4 split.
// ---------------------------------------------------------------------------
__global__ void __launch_bounds__(HIST_THREADS, 2) fused_kernel(
    const float4* __restrict__ feat_s, const float4* __restrict__ feat_t,
    float* __restrict__ out) {

    __shared__ unsigned int sh[NBINS][32];   // 32 KB, bank-exclusive columns

    #pragma unroll
    for (int i = threadIdx.x; i < NBINS * 32; i += HIST_THREADS)
        (&sh[0][0])[i] = 0u;
    __syncthreads();

    const float4* __restrict__ src = (blockIdx.z == 0) ? feat_s : feat_t;
    const int batch = blockIdx.y;
    const size_t base = (size_t)batch * F4_PER_BATCH
                      + (size_t)blockIdx.x * F4_PER_CHUNK;
    const int warp = threadIdx.x >> 5;
    const int lane = threadIdx.x & 31;

    const float4* gw = src + base + (size_t)warp * F4_PER_WARP;

    if (warp < SMEM_WARPS) {
        // ============== smem-atomic path (SM ATOMS unit) ==============
        #pragma unroll 1
        for (int it = 0; it < WARP_ITERS; it += 8) {
            float4 v[8];
            #pragma unroll
            for (int k = 0; k < 8; k++)
                v[k] = __ldcs(&gw[(it + k) * 32 + lane]);
            #pragma unroll
            for (int k = 0; k < 8; k++) {
                atomicAdd(&sh[bin_of(v[k].x)][lane], 1u);
                atomicAdd(&sh[bin_of(v[k].y)][lane], 1u);
                atomicAdd(&sh[bin_of(v[k].z)][lane], 1u);
                atomicAdd(&sh[bin_of(v[k].w)][lane], 1u);
            }
        }
    } else {
        // ============== global RED.ADD path (LTS atomic units) ==============
        unsigned int* __restrict__ dir = &g_dir[blockIdx.z][batch][0];
        #pragma unroll 1
        for (int it = 0; it < WARP_ITERS; it += 4) {
            float4 v[4];
            #pragma unroll
            for (int k = 0; k < 4; k++)
                v[k] = __ldcs(&gw[(it + k) * 32 + lane]);
            #pragma unroll
            for (int k = 0; k < 4; k++) {
                atomicAdd(dir + bin_of(v[k].x), 1u);   // no return -> RED.E.ADD
                atomicAdd(dir + bin_of(v[k].y), 1u);
                atomicAdd(dir + bin_of(v[k].z), 1u);
                atomicAdd(dir + bin_of(v[k].w), 1u);
            }
        }
    }
    __syncthreads();

    // reduce 32 lane-columns per bin; rotated reads stay conflict-free
    if (threadIdx.x < NBINS) {
        const int b = threadIdx.x;
        unsigned int sum = 0;
        #pragma unroll
        for (int i = 0; i < 32; i++) sum += sh[b][(i + b) & 31];
        g_part[blockIdx.z][batch][blockIdx.x][b] = sum;
    }
    __syncthreads();

    // ---- per-batch ticket ----
    __shared__ unsigned int s_bticket;
    if (threadIdx.x == 0) {
        __threadfence();   // orders g_part stores AND RED.ADDs before ticket
        s_bticket = atomicAdd(&g_bctr[batch], 1u);
    }
    __syncthreads();
    if (s_bticket != BLOCKS_PER_BATCH - 1) return;

    // ======== this block is last for its batch: compute KL(batch) ========
    __threadfence();  // acquire: all partials + RED.ADDs of this batch visible

    const int b = threadIdx.x;            // bin id for threads < NBINS
    __shared__ float rs[NBINS];
    __shared__ float rt[NBINS];

    float es = 0.f, et = 0.f, as_ = 0.f, at_ = 0.f;
    if (b < NBINS) {
        unsigned int cs = *((volatile unsigned int*)&g_dir[0][batch][b]);
        unsigned int ct = *((volatile unsigned int*)&g_dir[1][batch][b]);
        #pragma unroll
        for (int c = 0; c < CHUNKS; c++) {
            cs += *((volatile unsigned int*)&g_part[0][batch][c][b]);
            ct += *((volatile unsigned int*)&g_part[1][batch][c][b]);
        }
        // reset direct-hist words for the next graph replay (we own them now)
        g_dir[0][batch][b] = 0u;
        g_dir[1][batch][b] = 0u;

        as_ = (float)cs + 1e-8f;
        at_ = (float)ct + 1e-8f;
        es = sqrtf(sqrtf(as_));           // (a)^(1/T), T = 4
        et = sqrtf(sqrtf(at_));
        rs[b] = es; rt[b] = et;
    }
    __syncthreads();
    #pragma unroll
    for (int s = NBINS / 2; s > 0; s >>= 1) {
        if (b < s) { rs[b] += rs[b + s]; rt[b] += rt[b + s]; }
        __syncthreads();
    }
    float Ss = rs[0];
    float St = rt[0];
    __syncthreads();

    if (b < NBINS) {
        float pt = et / St;                                   // softmax target
        float diff = 0.25f * logf(at_ / as_) - logf(St / Ss); // log p_t - log p_s
        rs[b] = pt * diff;
    }
    __syncthreads();
    #pragma unroll
    for (int s = NBINS / 2; s > 0; s >>= 1) {
        if (b < s) rs[b] += rs[b + s];
        __syncthreads();
    }

    // publish per-batch KL, reset batch ticket, take global ticket
    __shared__ unsigned int s_ticket;
    if (threadIdx.x == 0) {
        g_kl[batch] = rs[0];
        g_bctr[batch] = 0;                 // ready for next graph replay
        __threadfence();
        s_ticket = atomicAdd(&g_ctr, 1u);
    }
    __syncthreads();
    if (s_ticket != NBATCH - 1) return;

    // ======== very last batch-winner: deterministic final sum ========
    __threadfence();
    __shared__ float red[NBATCH];
    if (threadIdx.x < NBATCH) red[threadIdx.x] = *((volatile float*)&g_kl[threadIdx.x]);
    __syncthreads();
    #pragma unroll
    for (int s = NBATCH / 2; s > 0; s >>= 1) {
        if (threadIdx.x < s) red[threadIdx.x] += red[threadIdx.x + s];
        __syncthreads();
    }
    if (threadIdx.x == 0) {
        out[0] = red[0] * (16.0f / (float)NBATCH);  // * T^2 / N
        g_ctr = 0;                                  // ready for next replay
    }
}

// ---------------------------------------------------------------------------
extern "C" void kernel_launch(void* const* d_in, const int* in_sizes, int n_in,
                              void* d_out, int out_size) {
    const float4* feat_s = (const float4*)d_in[0];
    const float4* feat_t = (const float4*)d_in[1];
    float* out = (float*)d_out;

    (void)in_sizes; (void)n_in; (void)out_size;

    dim3 grid(CHUNKS, NBATCH, 2);
    fused_kernel<<<grid, HIST_THREADS>>>(feat_s, feat_t, out);
}

// round 14
// speedup vs baseline: 3.4139x; 3.4139x over previous
#include <cuda_runtime.h>
#include <cstdint>

// Problem constants
#define NBATCH 64
#define NBINS  256
#define ELEMS_PER_BATCH (256*32*32)          // 262144 floats per batch per tensor
#define F4_PER_BATCH    (ELEMS_PER_BATCH/4)  // 65536 float4
#define CHUNKS 2                             // blocks per (batch, tensor)
#define F4_PER_CHUNK (F4_PER_BATCH/CHUNKS)   // 32768 float4 per block
#define HIST_THREADS 512
#define BLOCKS_PER_BATCH (2*CHUNKS)          // 4 (both tensors)
#define BATCH_F4 8                           // float4 held in regs per iteration

// Scratch (no device allocation allowed).
__device__ unsigned int g_part[2][NBATCH][CHUNKS][NBINS];
__device__ float        g_kl[NBATCH];
__device__ unsigned int g_bctr[NBATCH];      // per-batch tickets (reset by winner)
__device__ unsigned int g_ctr;               // global ticket (reset by final block)

// Exact float->small-int for integer-valued f in [0,255]: low byte of
// bits(f + 2^23). FADD+LOP instead of the F2I conversion pipe.
__device__ __forceinline__ unsigned int bin_of(float f) {
    return __float_as_uint(f + 8388608.0f) & 0xFFu;
}

// ---------------------------------------------------------------------------
// Single fused kernel. grid = (CHUNKS, NBATCH, 2) = 256 blocks, block = 512.
// 2 blocks/SM -> all 256 blocks resident (single wave), 64-reg budget.
// Inner loop: 8 float4 batched into registers (MLP>=8 DRAM lines/warp),
// then 32 bank-exclusive smem atomics (sh[bin][lane], zero conflicts).
// This configuration sits at the measured smem-ATOMS hardware floor
// (~4.2 lane-ops/cyc/SM); alternates (ballot, REDG, cp.async staging) all
// measured slower in R10-R13.
// ---------------------------------------------------------------------------
__global__ void __launch_bounds__(HIST_THREADS, 2) fused_kernel(
    const float4* __restrict__ feat_s, const float4* __restrict__ feat_t,
    float* __restrict__ out) {

    __shared__ unsigned int sh[NBINS][32];   // 32 KB: [bin][lane-column]

    #pragma unroll
    for (int i = threadIdx.x; i < NBINS * 32; i += HIST_THREADS)
        (&sh[0][0])[i] = 0u;
    __syncthreads();

    const float4* __restrict__ src = (blockIdx.z == 0) ? feat_s : feat_t;
    const int batch = blockIdx.y;
    const size_t base = (size_t)batch * F4_PER_BATCH
                      + (size_t)blockIdx.x * F4_PER_CHUNK;
    const int lane = threadIdx.x & 31;

    // 32768 float4 per block / 512 threads = 64 per thread = 8 iters x 8 loads
    #pragma unroll 1
    for (int it = 0; it < F4_PER_CHUNK; it += BATCH_F4 * HIST_THREADS) {
        float4 v[BATCH_F4];
        #pragma unroll
        for (int k = 0; k < BATCH_F4; k++)
            v[k] = __ldcs(&src[base + it + k * HIST_THREADS + threadIdx.x]);
        #pragma unroll
        for (int k = 0; k < BATCH_F4; k++) {
            atomicAdd(&sh[bin_of(v[k].x)][lane], 1u);
            atomicAdd(&sh[bin_of(v[k].y)][lane], 1u);
            atomicAdd(&sh[bin_of(v[k].z)][lane], 1u);
            atomicAdd(&sh[bin_of(v[k].w)][lane], 1u);
        }
    }
    __syncthreads();

    // reduce 32 lane-columns per bin; rotated reads keep banks conflict-free
    if (threadIdx.x < NBINS) {
        const int b = threadIdx.x;
        unsigned int sum = 0;
        #pragma unroll
        for (int i = 0; i < 32; i++) sum += sh[b][(i + b) & 31];
        g_part[blockIdx.z][batch][blockIdx.x][b] = sum;
    }
    __syncthreads();

    // ---- per-batch ticket ----
    __shared__ unsigned int s_bticket;
    if (threadIdx.x == 0) {
        __threadfence();
        s_bticket = atomicAdd(&g_bctr[batch], 1u);
    }
    __syncthreads();
    if (s_bticket != BLOCKS_PER_BATCH - 1) return;

    // ======== this block is last for its batch: compute KL(batch) ========
    __threadfence();  // acquire: make all partials of this batch visible

    const int b = threadIdx.x;            // bin id for threads < NBINS
    __shared__ float rs[NBINS];
    __shared__ float rt[NBINS];

    float es = 0.f, et = 0.f, as_ = 0.f, at_ = 0.f;
    if (b < NBINS) {
        unsigned int cs = 0, ct = 0;
        #pragma unroll
        for (int c = 0; c < CHUNKS; c++) {
            cs += *((volatile unsigned int*)&g_part[0][batch][c][b]);
            ct += *((volatile unsigned int*)&g_part[1][batch][c][b]);
        }
        as_ = (float)cs + 1e-8f;
        at_ = (float)ct + 1e-8f;
        es = sqrtf(sqrtf(as_));           // (a)^(1/T), T = 4
        et = sqrtf(sqrtf(at_));
        rs[b] = es; rt[b] = et;
    }
    __syncthreads();
    #pragma unroll
    for (int s = NBINS / 2; s > 0; s >>= 1) {
        if (b < s) { rs[b] += rs[b + s]; rt[b] += rt[b + s]; }
        __syncthreads();
    }
    float Ss = rs[0];
    float St = rt[0];
    __syncthreads();

    if (b < NBINS) {
        float pt = et / St;                                   // softmax target
        float diff = 0.25f * logf(at_ / as_) - logf(St / Ss); // log p_t - log p_s
        rs[b] = pt * diff;
    }
    __syncthreads();
    #pragma unroll
    for (int s = NBINS / 2; s > 0; s >>= 1) {
        if (b < s) rs[b] += rs[b + s];
        __syncthreads();
    }

    // publish per-batch KL, reset batch ticket, take global ticket
    __shared__ unsigned int s_ticket;
    if (threadIdx.x == 0) {
        g_kl[batch] = rs[0];
        g_bctr[batch] = 0;                 // ready for next graph replay
        __threadfence();
        s_ticket = atomicAdd(&g_ctr, 1u);
    }
    __syncthreads();
    if (s_ticket != NBATCH - 1) return;

    // ======== very last batch-winner: deterministic final sum ========
    __threadfence();
    __shared__ float red[NBATCH];
    if (threadIdx.x < NBATCH) red[threadIdx.x] = *((volatile float*)&g_kl[threadIdx.x]);
    __syncthreads();
    #pragma unroll
    for (int s = NBATCH / 2; s > 0; s >>= 1) {
        if (threadIdx.x < s) red[threadIdx.x] += red[threadIdx.x + s];
        __syncthreads();
    }
    if (threadIdx.x == 0) {
        out[0] = red[0] * (16.0f / (float)NBATCH);  // * T^2 / N
        g_ctr = 0;                                  // ready for next replay
    }
}

// ---------------------------------------------------------------------------
extern "C" void kernel_launch(void* const* d_in, const int* in_sizes, int n_in,
                              void* d_out, int out_size) {
    const float4* feat_s = (const float4*)d_in[0];
    const float4* feat_t = (const float4*)d_in[1];
    float* out = (float*)d_out;

    (void)in_sizes; (void)n_in; (void)out_size;

    dim3 grid(CHUNKS, NBATCH, 2);
    fused_kernel<<<grid, HIST_THREADS>>>(feat_s, feat_t, out);
}

// round 15
// speedup vs baseline: 3.4550x; 1.0121x over previous
#include <cuda_runtime.h>
#include <cstdint>

// Problem constants
#define NBATCH 64
#define NBINS  256
#define ELEMS_PER_BATCH (256*32*32)          // 262144 floats per batch per tensor
#define F4_PER_BATCH    (ELEMS_PER_BATCH/4)  // 65536 float4
#define CHUNKS 2                             // blocks per (batch, tensor)
#define F4_PER_CHUNK (F4_PER_BATCH/CHUNKS)   // 32768 float4 per block
#define HIST_THREADS 512
#define BLOCKS_PER_BATCH (2*CHUNKS)          // 4 (both tensors)
#define BF4 4                                // float4 per pipeline stage
#define STEP (BF4*HIST_THREADS)              // f4 consumed per stage
#define NSTEPS (F4_PER_CHUNK/STEP)           // 16 stages per block

// Scratch (no device allocation allowed).
__device__ unsigned int g_part[2][NBATCH][CHUNKS][NBINS];
__device__ float        g_kl[NBATCH];
__device__ unsigned int g_bctr[NBATCH];      // per-batch tickets (reset by winner)
__device__ unsigned int g_ctr;               // global ticket (reset by final block)

// Exact float->small-int for integer-valued f in [0,255]: low byte of
// bits(f + 2^23). FADD+LOP instead of the F2I conversion pipe.
__device__ __forceinline__ unsigned int bin_of(float f) {
    return __float_as_uint(f + 8388608.0f) & 0xFFu;
}

// ---------------------------------------------------------------------------
// Single fused kernel. grid = (CHUNKS, NBATCH, 2) = 256 blocks, block = 512.
// 2 blocks/SM (single resident wave), 64-reg budget.
// Software-pipelined register double buffer (4 float4 per stage, 2 stages):
// the next stage's LDG.128s are issued BEFORE the current stage's 16 smem
// atomics, so the ATOMS unit (the measured hardware wall: 1 warp-ATOMS /
// 32cyc / SMSP -> ~4 lane-ops/cyc/SM) never drains waiting on memory.
// Hist layout sh[bin][lane]: bank-exclusive, conflict-free by construction.
// ---------------------------------------------------------------------------
__global__ void __launch_bounds__(HIST_THREADS, 2) fused_kernel(
    const float4* __restrict__ feat_s, const float4* __restrict__ feat_t,
    float* __restrict__ out) {

    __shared__ unsigned int sh[NBINS][32];   // 32 KB: [bin][lane-column]

    #pragma unroll
    for (int i = threadIdx.x; i < NBINS * 32; i += HIST_THREADS)
        (&sh[0][0])[i] = 0u;
    __syncthreads();

    const float4* __restrict__ src = (blockIdx.z == 0) ? feat_s : feat_t;
    const int batch = blockIdx.y;
    const size_t base = (size_t)batch * F4_PER_BATCH
                      + (size_t)blockIdx.x * F4_PER_CHUNK;
    const int lane = threadIdx.x & 31;
    const float4* g = src + base + threadIdx.x;

    float4 a[BF4], b[BF4];

    // prologue: stage 0 into 'a'
    #pragma unroll
    for (int k = 0; k < BF4; k++)
        a[k] = __ldcs(&g[k * HIST_THREADS]);

    // main: unrolled x2, alternating buffers; loads for stage s+1 are issued
    // before the atomics of stage s.
    #pragma unroll 1
    for (int s = 0; s < NSTEPS - 2; s += 2) {
        const float4* gn1 = g + (size_t)(s + 1) * STEP;
        #pragma unroll
        for (int k = 0; k < BF4; k++) b[k] = __ldcs(&gn1[k * HIST_THREADS]);
        #pragma unroll
        for (int k = 0; k < BF4; k++) {
            atomicAdd(&sh[bin_of(a[k].x)][lane], 1u);
            atomicAdd(&sh[bin_of(a[k].y)][lane], 1u);
            atomicAdd(&sh[bin_of(a[k].z)][lane], 1u);
            atomicAdd(&sh[bin_of(a[k].w)][lane], 1u);
        }
        const float4* gn2 = g + (size_t)(s + 2) * STEP;
        #pragma unroll
        for (int k = 0; k < BF4; k++) a[k] = __ldcs(&gn2[k * HIST_THREADS]);
        #pragma unroll
        for (int k = 0; k < BF4; k++) {
            atomicAdd(&sh[bin_of(b[k].x)][lane], 1u);
            atomicAdd(&sh[bin_of(b[k].y)][lane], 1u);
            atomicAdd(&sh[bin_of(b[k].z)][lane], 1u);
            atomicAdd(&sh[bin_of(b[k].w)][lane], 1u);
        }
    }
    // epilogue: stages NSTEPS-2 (in 'a') and NSTEPS-1
    {
        const float4* gn = g + (size_t)(NSTEPS - 1) * STEP;
        #pragma unroll
        for (int k = 0; k < BF4; k++) b[k] = __ldcs(&gn[k * HIST_THREADS]);
        #pragma unroll
        for (int k = 0; k < BF4; k++) {
            atomicAdd(&sh[bin_of(a[k].x)][lane], 1u);
            atomicAdd(&sh[bin_of(a[k].y)][lane], 1u);
            atomicAdd(&sh[bin_of(a[k].z)][lane], 1u);
            atomicAdd(&sh[bin_of(a[k].w)][lane], 1u);
        }
        #pragma unroll
        for (int k = 0; k < BF4; k++) {
            atomicAdd(&sh[bin_of(b[k].x)][lane], 1u);
            atomicAdd(&sh[bin_of(b[k].y)][lane], 1u);
            atomicAdd(&sh[bin_of(b[k].z)][lane], 1u);
            atomicAdd(&sh[bin_of(b[k].w)][lane], 1u);
        }
    }
    __syncthreads();

    // reduce 32 lane-columns per bin; rotated reads keep banks conflict-free
    if (threadIdx.x < NBINS) {
        const int bb = threadIdx.x;
        unsigned int sum = 0;
        #pragma unroll
        for (int i = 0; i < 32; i++) sum += sh[bb][(i + bb) & 31];
        g_part[blockIdx.z][batch][blockIdx.x][bb] = sum;
    }
    __syncthreads();

    // ---- per-batch ticket ----
    __shared__ unsigned int s_bticket;
    if (threadIdx.x == 0) {
        __threadfence();
        s_bticket = atomicAdd(&g_bctr[batch], 1u);
    }
    __syncthreads();
    if (s_bticket != BLOCKS_PER_BATCH - 1) return;

    // ======== this block is last for its batch: compute KL(batch) ========
    __threadfence();  // acquire: make all partials of this batch visible

    const int bn = threadIdx.x;           // bin id for threads < NBINS
    __shared__ float rs[NBINS];
    __shared__ float rt[NBINS];

    float es = 0.f, et = 0.f, as_ = 0.f, at_ = 0.f;
    if (bn < NBINS) {
        unsigned int cs = 0, ct = 0;
        #pragma unroll
        for (int c = 0; c < CHUNKS; c++) {
            cs += *((volatile unsigned int*)&g_part[0][batch][c][bn]);
            ct += *((volatile unsigned int*)&g_part[1][batch][c][bn]);
        }
        as_ = (float)cs + 1e-8f;
        at_ = (float)ct + 1e-8f;
        es = sqrtf(sqrtf(as_));           // (a)^(1/T), T = 4
        et = sqrtf(sqrtf(at_));
        rs[bn] = es; rt[bn] = et;
    }
    __syncthreads();
    #pragma unroll
    for (int s = NBINS / 2; s > 0; s >>= 1) {
        if (bn < s) { rs[bn] += rs[bn + s]; rt[bn] += rt[bn + s]; }
        __syncthreads();
    }
    float Ss = rs[0];
    float St = rt[0];
    __syncthreads();

    if (bn < NBINS) {
        float pt = et / St;                                   // softmax target
        float diff = 0.25f * logf(at_ / as_) - logf(St / Ss); // log p_t - log p_s
        rs[bn] = pt * diff;
    }
    __syncthreads();
    #pragma unroll
    for (int s = NBINS / 2; s > 0; s >>= 1) {
        if (bn < s) rs[bn] += rs[bn + s];
        __syncthreads();
    }

    // publish per-batch KL, reset batch ticket, take global ticket
    __shared__ unsigned int s_ticket;
    if (threadIdx.x == 0) {
        g_kl[batch] = rs[0];
        g_bctr[batch] = 0;                 // ready for next graph replay
        __threadfence();
        s_ticket = atomicAdd(&g_ctr, 1u);
    }
    __syncthreads();
    if (s_ticket != NBATCH - 1) return;

    // ======== very last batch-winner: deterministic final sum ========
    __threadfence();
    __shared__ float red[NBATCH];
    if (threadIdx.x < NBATCH) red[threadIdx.x] = *((volatile float*)&g_kl[threadIdx.x]);
    __syncthreads();
    #pragma unroll
    for (int s = NBATCH / 2; s > 0; s >>= 1) {
        if (threadIdx.x < s) red[threadIdx.x] += red[threadIdx.x + s];
        __syncthreads();
    }
    if (threadIdx.x == 0) {
        out[0] = red[0] * (16.0f / (float)NBATCH);  // * T^2 / N
        g_ctr = 0;                                  // ready for next replay
    }
}

// ---------------------------------------------------------------------------
extern "C" void kernel_launch(void* const* d_in, const int* in_sizes, int n_in,
                              void* d_out, int out_size) {
    const float4* feat_s = (const float4*)d_in[0];
    const float4* feat_t = (const float4*)d_in[1];
    float* out = (float*)d_out;

    (void)in_sizes; (void)n_in; (void)out_size;

    dim3 grid(CHUNKS, NBATCH, 2);
    fused_kernel<<<grid, HIST_THREADS>>>(feat_s, feat_t, out);
}